// round 14
// baseline (speedup 1.0000x reference)
#include <cuda_runtime.h>
#include <math.h>

// Problem constants
#define B   32
#define QL  16
#define KL  8192
#define D   512
#define INV_SQRT_D 0.044194173824159216f   // 1/sqrt(512)

// score kernel: av-style column streaming
#define KSPLIT_S 32
#define KCHUNK_S (KL / KSPLIT_S)     // 256 rows per block
#define TROWS    16                  // rows per smem tile (R12: 8 -> 16)
#define NTILES   (KCHUNK_S / TROWS)  // 16
#define ZPB      4                   // z partials per block (one per warp)

// av kernel split
#define KSPLIT_V 32
#define KCHUNK_V (KL / KSPLIT_V)     // 256

// Scratch (device globals; allocations forbidden)
__device__ float g_w[B * KL];                      // 1 MB: p_k = exp(s_k)*t_k
__device__ float g_z[B * KSPLIT_S * ZPB];          // per-(block,warp) z partials
__device__ float g_acc[B * KSPLIT_V * D];          // 2 MB: weighted-V partials

// ---------------------------------------------------------------------------
// Kernel A: p[b,k] = exp((q0.key[b,k])/sqrt(D)*t) * t  — av-style streaming.
// Thread t owns float4 column t, streams rows sequentially. 16-row tiles:
// 16 independent LDG.128 issued per iteration, half the barrier/reduce
// interruptions of the 8-row version. Double-buffered smem partial tiles;
// the cross-thread reduction overlaps the next tile's prefetch.
// grid (KSPLIT_S, B), block 128 (4 warps; warp reduces 4 rows per tile).
// ---------------------------------------------------------------------------
__global__ void __launch_bounds__(128, 5)
score_kernel(const float* __restrict__ q,
             const float* __restrict__ key,
             const float* __restrict__ trust)
{
    const int b   = blockIdx.y;
    const int k0  = blockIdx.x * KCHUNK_S;
    const int tid = threadIdx.x;
    const int warp = tid >> 5;
    const int lane = tid & 31;

    __shared__ __align__(16) float ps[2][TROWS][128];   // 16 KB partial tiles
    __shared__ float ts[KCHUNK_S];                      // 1 KB trust chunk

    // q column held in registers for the whole kernel
    const float4 q4 = ((const float4*)(q + (size_t)b * QL * D))[tid];

    for (int i = tid; i < KCHUNK_S; i += 128)
        ts[i] = trust[(size_t)b * KL + k0 + i];

    // thread's column stream: row stride = D/4 = 128 float4
    const float4* kb = (const float4*)(key + ((size_t)b * KL + k0) * D) + tid;
    float* wb = g_w + (size_t)b * KL + k0;

    float zloc = 0.0f;          // valid on lane 0 of each warp
    float4 r[TROWS];

    // prologue: tile 0 -> buf 0
    #pragma unroll
    for (int j = 0; j < TROWS; j++) r[j] = kb[(size_t)j * (D / 4)];
    #pragma unroll
    for (int j = 0; j < TROWS; j++)
        ps[0][j][tid] = (r[j].x * q4.x + r[j].y * q4.y)
                      + (r[j].z * q4.z + r[j].w * q4.w);
    __syncthreads();

    for (int t = 0; t < NTILES; t++) {
        // prefetch next tile (16 independent, sequential LDG.128)
        if (t + 1 < NTILES) {
            const float4* kn = kb + (size_t)(t + 1) * TROWS * (D / 4);
            #pragma unroll
            for (int j = 0; j < TROWS; j++) r[j] = kn[(size_t)j * (D / 4)];
        }

        // reduce tile t: warp w handles rows 4w .. 4w+3
        const int buf = t & 1;
        #pragma unroll
        for (int rr = 0; rr < 4; rr++) {
            const int row = warp * 4 + rr;
            float4 v = ((const float4*)ps[buf][row])[lane];
            float s = (v.x + v.y) + (v.z + v.w);
            #pragma unroll
            for (int o = 16; o > 0; o >>= 1)
                s += __shfl_xor_sync(0xffffffffu, s, o);
            if (lane == 0) {
                const int gk = t * TROWS + row;
                const float tt = ts[gk];
                const float p = __expf(s * INV_SQRT_D * tt) * tt;
                wb[gk] = p;
                zloc += p;
            }
        }

        // stage next tile's partials into the other buffer
        if (t + 1 < NTILES) {
            const int nbuf = (t + 1) & 1;
            #pragma unroll
            for (int j = 0; j < TROWS; j++)
                ps[nbuf][j][tid] = (r[j].x * q4.x + r[j].y * q4.y)
                                 + (r[j].z * q4.z + r[j].w * q4.w);
        }
        __syncthreads();
    }

    if (lane == 0)
        g_z[(size_t)(b * KSPLIT_S + blockIdx.x) * ZPB + warp] = zloc;
}

// ---------------------------------------------------------------------------
// Kernel B: split-K weighted value sum (unnormalized weights). UNCHANGED —
// the >=7 TB/s reference pattern, no tail work attached (R11 lesson).
// grid (KSPLIT_V, B), block 128.
// ---------------------------------------------------------------------------
__global__ void __launch_bounds__(128)
av_kernel(const float* __restrict__ value)
{
    const int b  = blockIdx.y;
    const int k0 = blockIdx.x * KCHUNK_V;

    __shared__ float ws[KCHUNK_V];
    for (int i = threadIdx.x; i < KCHUNK_V; i += 128)
        ws[i] = g_w[b * KL + k0 + i];
    __syncthreads();

    const float4* vb = (const float4*)(value + ((size_t)b * KL + k0) * D) + threadIdx.x;

    float4 acc = make_float4(0.0f, 0.0f, 0.0f, 0.0f);
    #pragma unroll 16
    for (int kk = 0; kk < KCHUNK_V; kk++) {
        float4 v = vb[(size_t)kk * (D / 4)];
        float  w = ws[kk];
        acc.x += w * v.x;
        acc.y += w * v.y;
        acc.z += w * v.z;
        acc.w += w * v.w;
    }

    float4* out4 = (float4*)(g_acc + ((size_t)(b * KSPLIT_V + blockIdx.x)) * D);
    out4[threadIdx.x] = acc;
}

// ---------------------------------------------------------------------------
// Kernel C: out[b,d] = (sum_i acc_i[d]) / (sum_j z_j)
// grid (128), block 128. 128 z partials per batch, fixed-order sum.
// ---------------------------------------------------------------------------
__global__ void __launch_bounds__(128)
reduce_kernel(float* __restrict__ out)
{
    const int idx = blockIdx.x * 128 + threadIdx.x;   // b*D + d
    const int b = idx >> 9;                           // /512
    __shared__ float invZ_s;

    if (threadIdx.x < 32) {
        const float* zb = g_z + (size_t)b * KSPLIT_S * ZPB;   // 128 entries
        float z = 0.0f;
        #pragma unroll
        for (int i = 0; i < 4; i++) z += zb[threadIdx.x + i * 32];
        #pragma unroll
        for (int o = 16; o > 0; o >>= 1)
            z += __shfl_xor_sync(0xffffffffu, z, o);
        if (threadIdx.x == 0) invZ_s = 1.0f / z;
    }
    __syncthreads();

    float acc = 0.0f;
    #pragma unroll
    for (int i = 0; i < KSPLIT_V; i++)
        acc += g_acc[(size_t)(b * KSPLIT_V + i) * D + (idx & (D - 1))];
    out[idx] = acc * invZ_s;
}

// ---------------------------------------------------------------------------
extern "C" void kernel_launch(void* const* d_in, const int* in_sizes, int n_in,
                              void* d_out, int out_size)
{
    const float* query = (const float*)d_in[0];   // (B, QL, D)
    const float* key   = (const float*)d_in[1];   // (B, KL, D)
    const float* value = (const float*)d_in[2];   // (B, KL, D)
    const float* trust = (const float*)d_in[3];   // (B, 1, KL)
    float* out = (float*)d_out;                   // (B, 1, D)

    (void)in_sizes; (void)n_in; (void)out_size;

    dim3 g1(KSPLIT_S, B);
    score_kernel<<<g1, 128>>>(query, key, trust);

    dim3 g2(KSPLIT_V, B);
    av_kernel<<<g2, 128>>>(value);

    reduce_kernel<<<(B * D) / 128, 128>>>(out);
}

// round 15
// speedup vs baseline: 1.0490x; 1.0490x over previous
#include <cuda_runtime.h>
#include <math.h>

// Problem constants
#define B   32
#define QL  16
#define KL  8192
#define D   512
#define INV_SQRT_D 0.044194173824159216f   // 1/sqrt(512)

// score kernel: av-style column streaming, 256 threads / 2 row-groups
#define KSPLIT_S 32
#define KCHUNK_S (KL / KSPLIT_S)     // 256 rows per block
#define TROWS    16                  // rows per smem tile (8 per thread-group)
#define RPT      8                   // rows per thread per tile (register batch)
#define NTILES   (KCHUNK_S / TROWS)  // 16
#define ZPB      8                   // z partials per block (one per warp)

// av kernel split
#define KSPLIT_V 32
#define KCHUNK_V (KL / KSPLIT_V)     // 256

// Scratch (device globals; allocations forbidden)
__device__ float g_w[B * KL];                      // 1 MB: p_k = exp(s_k)*t_k
__device__ float g_z[B * KSPLIT_S * ZPB];          // per-(block,warp) z partials
__device__ float g_acc[B * KSPLIT_V * D];          // 2 MB: weighted-V partials

// ---------------------------------------------------------------------------
// Kernel A: p[b,k] = exp((q0.key[b,k])/sqrt(D)*t) * t — column streaming.
// 256 threads: group g = tid>>7 handles rows of parity g; thread owns float4
// column (tid&127). Per tile of 16 rows each thread loads 8 float4 (same
// register batch as the proven R10 config -> regs ~62, occ 50%), but barriers
// per chunk halve (16 vs 32). Double-buffered smem partial tiles; reduction
// overlaps next tile's prefetch.
// grid (KSPLIT_S, B), block 256 (8 warps; warp reduces 2 rows per tile).
// ---------------------------------------------------------------------------
__global__ void __launch_bounds__(256, 4)
score_kernel(const float* __restrict__ q,
             const float* __restrict__ key,
             const float* __restrict__ trust)
{
    const int b    = blockIdx.y;
    const int k0   = blockIdx.x * KCHUNK_S;
    const int tid  = threadIdx.x;
    const int g    = tid >> 7;          // row-parity group 0/1
    const int c    = tid & 127;         // float4 column
    const int warp = tid >> 5;
    const int lane = tid & 31;

    __shared__ __align__(16) float ps[2][TROWS][128];   // 16 KB partial tiles
    __shared__ float ts[KCHUNK_S];                      // 1 KB trust chunk

    // q column held in registers for the whole kernel
    const float4 q4 = ((const float4*)(q + (size_t)b * QL * D))[c];

    for (int i = tid; i < KCHUNK_S; i += 256)
        ts[i] = trust[(size_t)b * KL + k0 + i];

    // thread's column stream: this thread covers rows 2j+g, column c
    const float4* kb = (const float4*)(key + ((size_t)b * KL + k0) * D) + c
                     + (size_t)g * (D / 4);            // row parity offset
    float* wb = g_w + (size_t)b * KL + k0;

    float zloc = 0.0f;          // valid on lane 0 of each warp
    float4 r[RPT];

    // prologue: tile 0 -> buf 0  (thread's rows: 2j+g, j=0..7)
    #pragma unroll
    for (int j = 0; j < RPT; j++) r[j] = kb[(size_t)(2 * j) * (D / 4)];
    #pragma unroll
    for (int j = 0; j < RPT; j++)
        ps[0][2 * j + g][c] = (r[j].x * q4.x + r[j].y * q4.y)
                            + (r[j].z * q4.z + r[j].w * q4.w);
    __syncthreads();

    for (int t = 0; t < NTILES; t++) {
        // prefetch next tile (8 independent, sequential LDG.128 per thread)
        if (t + 1 < NTILES) {
            const float4* kn = kb + (size_t)(t + 1) * TROWS * (D / 4);
            #pragma unroll
            for (int j = 0; j < RPT; j++) r[j] = kn[(size_t)(2 * j) * (D / 4)];
        }

        // reduce tile t: warp w handles rows 2w, 2w+1
        const int buf = t & 1;
        #pragma unroll
        for (int rr = 0; rr < 2; rr++) {
            const int row = warp * 2 + rr;
            float4 v = ((const float4*)ps[buf][row])[lane];
            float s = (v.x + v.y) + (v.z + v.w);
            #pragma unroll
            for (int o = 16; o > 0; o >>= 1)
                s += __shfl_xor_sync(0xffffffffu, s, o);
            if (lane == 0) {
                const int gk = t * TROWS + row;
                const float tt = ts[gk];
                const float p = __expf(s * INV_SQRT_D * tt) * tt;
                wb[gk] = p;
                zloc += p;
            }
        }

        // stage next tile's partials into the other buffer
        if (t + 1 < NTILES) {
            const int nbuf = (t + 1) & 1;
            #pragma unroll
            for (int j = 0; j < RPT; j++)
                ps[nbuf][2 * j + g][c] = (r[j].x * q4.x + r[j].y * q4.y)
                                       + (r[j].z * q4.z + r[j].w * q4.w);
        }
        __syncthreads();
    }

    if (lane == 0)
        g_z[(size_t)(b * KSPLIT_S + blockIdx.x) * ZPB + warp] = zloc;
}

// ---------------------------------------------------------------------------
// Kernel B: split-K weighted value sum (unnormalized weights). UNCHANGED —
// the >=7 TB/s reference pattern, no tail work attached (R11 lesson).
// grid (KSPLIT_V, B), block 128.
// ---------------------------------------------------------------------------
__global__ void __launch_bounds__(128)
av_kernel(const float* __restrict__ value)
{
    const int b  = blockIdx.y;
    const int k0 = blockIdx.x * KCHUNK_V;

    __shared__ float ws[KCHUNK_V];
    for (int i = threadIdx.x; i < KCHUNK_V; i += 128)
        ws[i] = g_w[b * KL + k0 + i];
    __syncthreads();

    const float4* vb = (const float4*)(value + ((size_t)b * KL + k0) * D) + threadIdx.x;

    float4 acc = make_float4(0.0f, 0.0f, 0.0f, 0.0f);
    #pragma unroll 16
    for (int kk = 0; kk < KCHUNK_V; kk++) {
        float4 v = vb[(size_t)kk * (D / 4)];
        float  w = ws[kk];
        acc.x += w * v.x;
        acc.y += w * v.y;
        acc.z += w * v.z;
        acc.w += w * v.w;
    }

    float4* out4 = (float4*)(g_acc + ((size_t)(b * KSPLIT_V + blockIdx.x)) * D);
    out4[threadIdx.x] = acc;
}

// ---------------------------------------------------------------------------
// Kernel C: out[b,d] = (sum_i acc_i[d]) / (sum_j z_j)
// grid (128), block 128. 256 z partials per batch, fixed-order sum.
// ---------------------------------------------------------------------------
__global__ void __launch_bounds__(128)
reduce_kernel(float* __restrict__ out)
{
    const int idx = blockIdx.x * 128 + threadIdx.x;   // b*D + d
    const int b = idx >> 9;                           // /512
    __shared__ float invZ_s;

    if (threadIdx.x < 32) {
        const float* zb = g_z + (size_t)b * KSPLIT_S * ZPB;   // 256 entries
        float z = 0.0f;
        #pragma unroll
        for (int i = 0; i < 8; i++) z += zb[threadIdx.x + i * 32];
        #pragma unroll
        for (int o = 16; o > 0; o >>= 1)
            z += __shfl_xor_sync(0xffffffffu, z, o);
        if (threadIdx.x == 0) invZ_s = 1.0f / z;
    }
    __syncthreads();

    float acc = 0.0f;
    #pragma unroll
    for (int i = 0; i < KSPLIT_V; i++)
        acc += g_acc[(size_t)(b * KSPLIT_V + i) * D + (idx & (D - 1))];
    out[idx] = acc * invZ_s;
}

// ---------------------------------------------------------------------------
extern "C" void kernel_launch(void* const* d_in, const int* in_sizes, int n_in,
                              void* d_out, int out_size)
{
    const float* query = (const float*)d_in[0];   // (B, QL, D)
    const float* key   = (const float*)d_in[1];   // (B, KL, D)
    const float* value = (const float*)d_in[2];   // (B, KL, D)
    const float* trust = (const float*)d_in[3];   // (B, 1, KL)
    float* out = (float*)d_out;                   // (B, 1, D)

    (void)in_sizes; (void)n_in; (void)out_size;

    dim3 g1(KSPLIT_S, B);
    score_kernel<<<g1, 256>>>(query, key, trust);

    dim3 g2(KSPLIT_V, B);
    av_kernel<<<g2, 128>>>(value);

    reduce_kernel<<<(B * D) / 128, 128>>>(out);
}